// round 4
// baseline (speedup 1.0000x reference)
#include <cuda_runtime.h>
#include <math.h>

#define Bb 64
#define Tt 512
#define INN 1024
#define Hh 1024

#define NB 128      // persistent blocks (1/SM, co-resident on 148+ SMs)
#define TPB 384     // 12 warps: warp -> (gate g = w/4, batch-quarter bq = w%4)

typedef unsigned long long ull;

// ---------------- scratch (device globals; no allocation allowed) ----------------
__device__ float g_pre[4ull * Tt * Bb * Hh];     // [gate][t][b][h]  (512 MB)
__device__ float ct_buf[2][Bb * Hh];             // ping-pong cell state
__device__ unsigned g_bar = 0;                   // grid barrier counter

// ---------------- fp32x2 packed helpers (FFMA2 = full-rate fp32 on sm_103a) ------
__device__ __forceinline__ ull pk2(float lo, float hi) {
    ull r; asm("mov.b64 %0, {%1,%2};" : "=l"(r) : "f"(lo), "f"(hi)); return r;
}
__device__ __forceinline__ void unpk2(ull v, float& lo, float& hi) {
    asm("mov.b64 {%0,%1}, %2;" : "=f"(lo), "=f"(hi) : "l"(v));
}
__device__ __forceinline__ void fma2(ull& d, ull a, ull b) {
    asm("fma.rn.f32x2 %0, %1, %2, %3;" : "=l"(d) : "l"(a), "l"(b), "l"(d));
}

// ---------------- init: cell state from c0 + barrier reset ----------------
__global__ void init_kernel(const float* __restrict__ c0) {
    int i = blockIdx.x * 256 + threadIdx.x;  // 65536 total
    ct_buf[0][i] = c0[i & (Hh - 1)];
    if (i == 0) g_bar = 0;
}

// ---------------- input projections: g_pre[gate][t][b][h] = x @ Wx^T + bias -----
__global__ __launch_bounds__(256) void proj_kernel(
    const float* __restrict__ x,
    const float* __restrict__ Wf, const float* __restrict__ Wi,
    const float* __restrict__ Wo, const float* __restrict__ Wc,
    const float* __restrict__ bf, const float* __restrict__ bi,
    const float* __restrict__ bo, const float* __restrict__ bc) {
    __shared__ float As[8][128];
    __shared__ float Bs[8][128];

    int gate = blockIdx.y >> 3;
    int n0 = (blockIdx.y & 7) * 128;
    int m0 = blockIdx.x * 128;
    const float* W    = (gate == 0) ? Wf : (gate == 1) ? Wi : (gate == 2) ? Wo : Wc;
    const float* bias = (gate == 0) ? bf : (gate == 1) ? bi : (gate == 2) ? bo : bc;

    int tid = threadIdx.x;
    int tx = tid & 15;   // n dir (x8)
    int ty = tid >> 4;   // m dir (x8)
    int lr = tid >> 1;
    int lc = (tid & 1) * 4;
    const float* Ag = x + (size_t)(m0 + lr) * INN + lc;
    const float* Bg = W + (size_t)(n0 + lr) * INN + lc;

    ull acc2[8][4];
#pragma unroll
    for (int i = 0; i < 8; i++)
#pragma unroll
        for (int j = 0; j < 4; j++) acc2[i][j] = 0ull;

    for (int k0 = 0; k0 < INN; k0 += 8) {
        float4 av = *(const float4*)(Ag + k0);
        float4 bv = *(const float4*)(Bg + k0);
        As[lc + 0][lr] = av.x; As[lc + 1][lr] = av.y;
        As[lc + 2][lr] = av.z; As[lc + 3][lr] = av.w;
        Bs[lc + 0][lr] = bv.x; Bs[lc + 1][lr] = bv.y;
        Bs[lc + 2][lr] = bv.z; Bs[lc + 3][lr] = bv.w;
        __syncthreads();
#pragma unroll
        for (int kk = 0; kk < 8; kk++) {
            float4 a0 = *(const float4*)&As[kk][ty * 8];
            float4 a1 = *(const float4*)&As[kk][ty * 8 + 4];
            float a[8] = {a0.x, a0.y, a0.z, a0.w, a1.x, a1.y, a1.z, a1.w};
            float4 b0 = *(const float4*)&Bs[kk][tx * 8];
            float4 b1 = *(const float4*)&Bs[kk][tx * 8 + 4];
            ull bp[4] = {pk2(b0.x, b0.y), pk2(b0.z, b0.w),
                         pk2(b1.x, b1.y), pk2(b1.z, b1.w)};
#pragma unroll
            for (int i = 0; i < 8; i++) {
                ull ap = pk2(a[i], a[i]);
#pragma unroll
                for (int j = 0; j < 4; j++) fma2(acc2[i][j], ap, bp[j]);
            }
        }
        __syncthreads();
    }

#pragma unroll
    for (int i = 0; i < 8; i++) {
        int r = m0 + ty * 8 + i;
        int b_ = r >> 9;         // T = 512
        int t_ = r & (Tt - 1);
        float* dst = g_pre + (((size_t)gate * Tt + t_) * Bb + b_) * Hh + n0 + tx * 8;
#pragma unroll
        for (int j = 0; j < 4; j++) {
            float lo, hi;
            unpk2(acc2[i][j], lo, hi);
            int hcol = n0 + tx * 8 + 2 * j;
            float v0 = lo + bias[hcol];
            float v1 = hi + bias[hcol + 1];
            if (gate == 3) { v0 = tanhf(v0); v1 = tanhf(v1); }
            dst[2 * j]     = v0;
            dst[2 * j + 1] = v1;
        }
    }
}

// ---------------- persistent recurrence: all 512 steps in ONE kernel ----------------
// 128 blocks x 384 threads. Block owns h-tile [h0, h0+8) for gates f,i,o over all 64 b.
// SMEM: weights (3x8x1024, loaded once), ct chunk (64x128, double-clocked via reg
// prefetch), r results (24x64). One grid barrier per step.
//
// SMEM pitches (bank-conflict checked vs 128B bank span):
//   Ws pitch 1028 floats (4112B): h-lane offsets h*16 mod 128 -> distinct, x4 bcast
//   cts pitch 132 floats (528B): bs-lane offsets bs*16 mod 128 -> distinct, x8 bcast
#define WS_PITCH 1028
#define CT_PITCH 132
#define RS_PITCH 68
#define SMEM_FLOATS (24 * WS_PITCH + 64 * CT_PITCH + 24 * RS_PITCH)

__global__ __launch_bounds__(TPB, 1) void rec_persist_kernel(
    const float* __restrict__ Wcf, const float* __restrict__ Wci,
    const float* __restrict__ Wco, const float* __restrict__ c0,
    float* __restrict__ out, int write_tail) {
    extern __shared__ float sm[];
    float* Ws  = sm;                        // [24][1028]
    float* cts = Ws + 24 * WS_PITCH;        // [64][132]
    float* rs  = cts + 64 * CT_PITCH;       // [24][68]

    int tid = threadIdx.x;
    int h0 = blockIdx.x * 8;

    // ---- preload recurrent weights into SMEM (once per launch) ----
    {
        const float* Wg0 = Wcf;  const float* Wg1 = Wci;  const float* Wg2 = Wco;
#pragma unroll 1
        for (int col = 0; col < 24; col++) {
            const float* src = ((col >> 3) == 0 ? Wg0 : (col >> 3) == 1 ? Wg1 : Wg2)
                               + (size_t)(h0 + (col & 7)) * Hh;
            float4* dst = (float4*)(Ws + col * WS_PITCH);
            for (int k = tid; k < Hh / 4; k += TPB)
                dst[k] = ((const float4*)src)[k];
        }
    }

    int w = tid >> 5, lane = tid & 31;
    int bq = w & 3;                  // batch quarter (16 b)
    int hl = lane >> 2, bs = lane & 3;
    int col = (w >> 2) * 8 + hl;     // gate*8 + h_local
    const float* wrow = Ws + col * WS_PITCH;

    // ---- register-carried cell state for pointwise threads ----
    float creg0 = 0.f, creg1 = 0.f;
    int pb = tid >> 2, phq = tid & 3;     // pointwise: batch, h-quarter (2 h each)
    if (tid < 256) {
        creg0 = c0[h0 + phq * 2 + 0];
        creg1 = c0[h0 + phq * 2 + 1];
    }
    __syncthreads();

    float4 pf[8];
    for (int t = 0; t < Tt; t++) {
        const float* ct_in = ct_buf[t & 1];
        float* ct_out = ct_buf[(t & 1) ^ 1];

        ull acc[4] = {0ull, 0ull, 0ull, 0ull};

        // prefetch ct chunk 0 (L2-only loads: ct written by other SMs)
        if (tid < 256) {
#pragma unroll
            for (int i = 0; i < 8; i++) {
                int j = i * 256 + tid;
                pf[i] = __ldcg((const float4*)ct_in + (j >> 5) * (Hh / 4) + (j & 31));
            }
        }

#pragma unroll 1
        for (int c = 0; c < 8; c++) {
            __syncthreads();
            if (tid < 256) {
#pragma unroll
                for (int i = 0; i < 8; i++) {
                    int j = i * 256 + tid;
                    *(float4*)(cts + (j >> 5) * CT_PITCH + (j & 31) * 4) = pf[i];
                }
            }
            __syncthreads();
            if (c < 7 && tid < 256) {
                int kc4 = (c + 1) * 32;
#pragma unroll
                for (int i = 0; i < 8; i++) {
                    int j = i * 256 + tid;
                    pf[i] = __ldcg((const float4*)ct_in + (j >> 5) * (Hh / 4) + kc4 + (j & 31));
                }
            }
            // compute this chunk: 32 k-quads
#pragma unroll 8
            for (int k4 = 0; k4 < 32; k4++) {
                ulonglong2 wv = *(const ulonglong2*)(wrow + c * 128 + k4 * 4);
#pragma unroll
                for (int bi = 0; bi < 4; bi++) {
                    int b = bq * 16 + bi * 4 + bs;
                    ulonglong2 cv = *(const ulonglong2*)(cts + b * CT_PITCH + k4 * 4);
                    fma2(acc[bi], cv.x, wv.x);
                    fma2(acc[bi], cv.y, wv.y);
                }
            }
        }

        // write r results to SMEM
#pragma unroll
        for (int bi = 0; bi < 4; bi++) {
            float lo, hi;
            unpk2(acc[bi], lo, hi);
            rs[col * RS_PITCH + bq * 16 + bi * 4 + bs] = lo + hi;
        }
        __syncthreads();

        // ---- pointwise LSTM update (block-local: all 3 gates present) ----
        if (tid < 256) {
#pragma unroll
            for (int hh = 0; hh < 2; hh++) {
                int hl2 = phq * 2 + hh;
                int hg = h0 + hl2;
                size_t gb = (size_t)t * Bb * Hh + (size_t)pb * Hh + hg;
                float gf = g_pre[gb];
                float gi = g_pre[(size_t)Tt * Bb * Hh + gb];
                float go = g_pre[2ull * Tt * Bb * Hh + gb];
                float tc = g_pre[3ull * Tt * Bb * Hh + gb];   // pre-tanh'd
                float rf = rs[(0 * 8 + hl2) * RS_PITCH + pb];
                float ri = rs[(1 * 8 + hl2) * RS_PITCH + pb];
                float ro = rs[(2 * 8 + hl2) * RS_PITCH + pb];
                float cprev = hh ? creg1 : creg0;
                float f  = 1.f / (1.f + __expf(-(gf + rf)));
                float ii = 1.f / (1.f + __expf(-(gi + ri)));
                float o  = 1.f / (1.f + __expf(-(go + ro)));
                float cn = f * cprev + ii * tc;
                float hv = o * tanhf(cn);
                if (hh) creg1 = cn; else creg0 = cn;
                ct_out[pb * Hh + hg] = cn;
                out[((size_t)pb * Tt + t) * Hh + hg] = hv;
                if (write_tail && t == Tt - 1)
                    out[(size_t)Bb * Tt * Hh + pb * Hh + hg] = hv;
            }
        }

        // ---- grid barrier: all ct_out writes visible before next step ----
        __syncthreads();
        __threadfence();
        if (tid == 0) {
            atomicAdd(&g_bar, 1u);    // result unused -> RED (no-return)
            unsigned target = (unsigned)(t + 1) * NB;
            while (*((volatile unsigned*)&g_bar) < target) { }
        }
        __syncthreads();
        __threadfence();              // gpu-scope fence: CCTL.IVALL (L1 invalidate)
    }
}

// ---------------- launch ----------------
extern "C" void kernel_launch(void* const* d_in, const int* in_sizes, int n_in,
                              void* d_out, int out_size) {
    const float* x   = (const float*)d_in[0];
    const float* Wxf = (const float*)d_in[1];
    const float* Wcf = (const float*)d_in[2];
    const float* bcf = (const float*)d_in[3];
    const float* Wxi = (const float*)d_in[4];
    const float* Wci = (const float*)d_in[5];
    const float* bci = (const float*)d_in[6];
    const float* Wxo = (const float*)d_in[7];
    const float* Wco = (const float*)d_in[8];
    const float* bco = (const float*)d_in[9];
    const float* Wxc = (const float*)d_in[10];
    const float* bxc = (const float*)d_in[11];
    const float* c0  = (const float*)d_in[12];
    float* out = (float*)d_out;
    int write_tail = (out_size >= Bb * Tt * Hh + Bb * Hh) ? 1 : 0;

    static int smem_set = 0;
    if (!smem_set) {
        cudaFuncSetAttribute(rec_persist_kernel,
                             cudaFuncAttributeMaxDynamicSharedMemorySize,
                             SMEM_FLOATS * (int)sizeof(float));
        smem_set = 1;
    }

    init_kernel<<<256, 256>>>(c0);
    proj_kernel<<<dim3(256, 32), 256>>>(x, Wxf, Wxi, Wxo, Wxc, bcf, bci, bco, bxc);
    rec_persist_kernel<<<NB, TPB, SMEM_FLOATS * sizeof(float)>>>(
        Wcf, Wci, Wco, c0, out, write_tail);
}

// round 6
// speedup vs baseline: 1.2073x; 1.2073x over previous
#include <cuda_runtime.h>
#include <math.h>

#define Bb 64
#define Tt 512
#define INN 1024
#define Hh 1024

#define NB 128      // persistent blocks
#define TPB 384     // 384 threads: tid = kg + 16*m, m = bg + 8*cg

typedef unsigned long long ull;

// ---------------- scratch (device globals; no allocation allowed) ----------------
__device__ __align__(16) float g_pre[4ull * Tt * Bb * Hh];  // [gate][t][b][h] (512 MB)
__device__ __align__(16) float ctT_buf[2][Hh * Bb];         // cell state, TRANSPOSED [h][b]
__device__ unsigned g_bar = 0;                              // grid barrier counter

// ---------------- fp32x2 packed helpers ----------------
__device__ __forceinline__ ull pk2(float lo, float hi) {
    ull r; asm("mov.b64 %0, {%1,%2};" : "=l"(r) : "f"(lo), "f"(hi)); return r;
}
__device__ __forceinline__ void unpk2(ull v, float& lo, float& hi) {
    asm("mov.b64 {%0,%1}, %2;" : "=f"(lo), "=f"(hi) : "l"(v));
}
__device__ __forceinline__ void fma2(ull& d, ull a, ull b) {
    asm("fma.rn.f32x2 %0, %1, %2, %3;" : "=l"(d) : "l"(a), "l"(b), "l"(d));
}
__device__ __forceinline__ void add2(ull& d, ull a) {
    asm("add.rn.f32x2 %0, %1, %2;" : "=l"(d) : "l"(d), "l"(a));
}

// ---------------- init: transposed cell state from c0 + barrier reset ----------------
__global__ void init_kernel(const float* __restrict__ c0) {
    int i = blockIdx.x * 256 + threadIdx.x;  // 65536 total; h = i>>6, b = i&63
    ctT_buf[0][i] = c0[i >> 6];
    if (i == 0) g_bar = 0;
}

// ---------------- input projections: g_pre[gate][t][b][h] = x @ Wx^T + bias -----
__global__ __launch_bounds__(256) void proj_kernel(
    const float* __restrict__ x,
    const float* __restrict__ Wf, const float* __restrict__ Wi,
    const float* __restrict__ Wo, const float* __restrict__ Wc,
    const float* __restrict__ bf, const float* __restrict__ bi,
    const float* __restrict__ bo, const float* __restrict__ bc) {
    __shared__ float As[8][128];
    __shared__ float Bs[8][128];

    int gate = blockIdx.y >> 3;
    int n0 = (blockIdx.y & 7) * 128;
    int m0 = blockIdx.x * 128;
    const float* W    = (gate == 0) ? Wf : (gate == 1) ? Wi : (gate == 2) ? Wo : Wc;
    const float* bias = (gate == 0) ? bf : (gate == 1) ? bi : (gate == 2) ? bo : bc;

    int tid = threadIdx.x;
    int tx = tid & 15;
    int ty = tid >> 4;
    int lr = tid >> 1;
    int lc = (tid & 1) * 4;
    const float* Ag = x + (size_t)(m0 + lr) * INN + lc;
    const float* Bg = W + (size_t)(n0 + lr) * INN + lc;

    ull acc2[8][4];
#pragma unroll
    for (int i = 0; i < 8; i++)
#pragma unroll
        for (int j = 0; j < 4; j++) acc2[i][j] = 0ull;

    for (int k0 = 0; k0 < INN; k0 += 8) {
        float4 av = *(const float4*)(Ag + k0);
        float4 bv = *(const float4*)(Bg + k0);
        As[lc + 0][lr] = av.x; As[lc + 1][lr] = av.y;
        As[lc + 2][lr] = av.z; As[lc + 3][lr] = av.w;
        Bs[lc + 0][lr] = bv.x; Bs[lc + 1][lr] = bv.y;
        Bs[lc + 2][lr] = bv.z; Bs[lc + 3][lr] = bv.w;
        __syncthreads();
#pragma unroll
        for (int kk = 0; kk < 8; kk++) {
            float4 a0 = *(const float4*)&As[kk][ty * 8];
            float4 a1 = *(const float4*)&As[kk][ty * 8 + 4];
            float a[8] = {a0.x, a0.y, a0.z, a0.w, a1.x, a1.y, a1.z, a1.w};
            float4 b0 = *(const float4*)&Bs[kk][tx * 8];
            float4 b1 = *(const float4*)&Bs[kk][tx * 8 + 4];
            ull bp[4] = {pk2(b0.x, b0.y), pk2(b0.z, b0.w),
                         pk2(b1.x, b1.y), pk2(b1.z, b1.w)};
#pragma unroll
            for (int i = 0; i < 8; i++) {
                ull ap = pk2(a[i], a[i]);
#pragma unroll
                for (int j = 0; j < 4; j++) fma2(acc2[i][j], ap, bp[j]);
            }
        }
        __syncthreads();
    }

#pragma unroll
    for (int i = 0; i < 8; i++) {
        int r = m0 + ty * 8 + i;
        int b_ = r >> 9;
        int t_ = r & (Tt - 1);
        float* dst = g_pre + (((size_t)gate * Tt + t_) * Bb + b_) * Hh + n0 + tx * 8;
#pragma unroll
        for (int j = 0; j < 4; j++) {
            float lo, hi;
            unpk2(acc2[i][j], lo, hi);
            int hcol = n0 + tx * 8 + 2 * j;
            float v0 = lo + bias[hcol];
            float v1 = hi + bias[hcol + 1];
            if (gate == 3) { v0 = tanhf(v0); v1 = tanhf(v1); }
            dst[2 * j]     = v0;
            dst[2 * j + 1] = v1;
        }
    }
}

// ---------------- persistent recurrence ----------------
// Block owns h-tile [h0,h0+8) x 3 gates = 24 cols, all 64 b.
// Thread (kg,cg,bg): 8x8 reg tile (8 b, 4 packed pairs x 8 cols), k = kg mod 16.
// SMEM: Ws[1024][26] weights (once), cts[128][66] ct chunk, rs[24][68], ctb[8][68].
// cts pitch 66 floats = 33 ull: kg*33 mod 16 distinct -> conflict-free LDS.64 reads.
// Staging stores use float2 (8B) since 66 % 4 != 0 (float4 would be misaligned).
#define WP  26
#define CTP 66
#define RSP 68
#define CBP 68
#define SMEM_FLOATS (1024 * WP + 128 * CTP + 24 * RSP + 8 * CBP)

__global__ __launch_bounds__(TPB, 1) void rec_persist_kernel(
    const float* __restrict__ Wcf, const float* __restrict__ Wci,
    const float* __restrict__ Wco, const float* __restrict__ c0,
    float* __restrict__ out, int write_tail) {
    extern __shared__ float sm[];
    float* Ws  = sm;                 // [1024][26]  Ws[k*WP+col]
    float* cts = Ws + 1024 * WP;     // [128][66]   cts[kl*CTP+b]
    float* rs  = cts + 128 * CTP;    // [24][68]
    float* ctb = rs + 24 * RSP;      // [8][68]

    int tid = threadIdx.x;
    int h0 = blockIdx.x * 8;

    // ---- weights into SMEM once: Ws[k][col] = W_gate[h0+col%8][k] ----
#pragma unroll 1
    for (int col = 0; col < 24; col++) {
        const float* src = ((col < 8) ? Wcf : (col < 16) ? Wci : Wco)
                           + (size_t)(h0 + (col & 7)) * Hh;
        for (int k = tid; k < Hh; k += TPB)
            Ws[k * WP + col] = src[k];
    }

    int kg = tid & 15, m = tid >> 4;
    int cg = m >> 3, bg = m & 7;

    // pointwise identity: b = tid>>2, h-quarter = tid&3 (2 h each)
    int pb = tid >> 2;
    int hq = tid & 3;
    float creg0 = 0.f, creg1 = 0.f;
    if (tid < 256) { creg0 = c0[h0 + hq * 2]; creg1 = c0[h0 + hq * 2 + 1]; }
    __syncthreads();

    float4 pf[6];
    for (int t = 0; t < Tt; t++) {
        const float* ct_in = ctT_buf[t & 1];
        float* ct_out = ctT_buf[(t & 1) ^ 1];

        // gate prefetch for pointwise (huge slack before use)
        float2 gv[4];
        if (tid < 256) {
            size_t gb = (size_t)t * Bb * Hh + (size_t)pb * Hh + h0 + hq * 2;
#pragma unroll
            for (int g = 0; g < 4; g++)
                gv[g] = __ldcg((const float2*)(g_pre + (size_t)g * Tt * Bb * Hh + gb));
        }

        // chunk 0 prefetch (contiguous 32KB: ctT[0:128][0:64])
        {
            const float4* src4 = (const float4*)ct_in;
#pragma unroll
            for (int i = 0; i < 6; i++) {
                int idx4 = tid + i * TPB;
                if (idx4 < 2048) pf[i] = __ldcg(src4 + idx4);
            }
        }

        ull acc[32];
#pragma unroll
        for (int q = 0; q < 32; q++) acc[q] = 0ull;

#pragma unroll 1
        for (int c = 0; c < 8; c++) {
            __syncthreads();
#pragma unroll
            for (int i = 0; i < 6; i++) {
                int idx4 = tid + i * TPB;
                if (idx4 < 2048) {
                    float* dst = cts + (idx4 >> 4) * CTP + (idx4 & 15) * 4;
                    *(float2*)dst       = make_float2(pf[i].x, pf[i].y);  // 8B-aligned
                    *(float2*)(dst + 2) = make_float2(pf[i].z, pf[i].w);
                }
            }
            __syncthreads();
            if (c < 7) {
                const float4* src4 = (const float4*)(ct_in + (c + 1) * 128 * 64);
#pragma unroll
                for (int i = 0; i < 6; i++) {
                    int idx4 = tid + i * TPB;
                    if (idx4 < 2048) pf[i] = __ldcg(src4 + idx4);
                }
            }
            // compute this chunk: k = c*128 + kg + 16j
#pragma unroll 2
            for (int j = 0; j < 8; j++) {
                int kl = kg + 16 * j;
                const float* wr = Ws + (c * 128 + kl) * WP + cg * 8;
                const float* cr = cts + kl * CTP + bg * 8;
                ull ctp[4];
#pragma unroll
                for (int p = 0; p < 4; p++) ctp[p] = *(const ull*)(cr + 2 * p);
#pragma unroll
                for (int ci = 0; ci < 8; ci++) {
                    float w = wr[ci];
                    ull wd = pk2(w, w);
#pragma unroll
                    for (int p = 0; p < 4; p++) fma2(acc[ci * 4 + p], ctp[p], wd);
                }
            }
        }

        // ---- butterfly reduce over kg (lanes 0-15 / 16-31 halves) ----
#pragma unroll
        for (int d = 1; d < 16; d <<= 1) {
#pragma unroll
            for (int q = 0; q < 32; q++) {
                ull o = __shfl_xor_sync(0xffffffffu, acc[q], d);
                add2(acc[q], o);
            }
        }
        // lane kg writes acc slots {2kg, 2kg+1} -> rs[col][b]
        {
            int q0 = kg * 2;
#pragma unroll
            for (int e = 0; e < 2; e++) {
                int q = q0 + e;
                int ci = q >> 2, p = q & 3;
                float lo, hi;
                unpk2(acc[q], lo, hi);
                float* dst = rs + (cg * 8 + ci) * RSP + bg * 8 + 2 * p;
                dst[0] = lo; dst[1] = hi;
            }
        }
        __syncthreads();

        // ---- pointwise LSTM update (block-local) ----
        if (tid < 256) {
#pragma unroll
            for (int hh = 0; hh < 2; hh++) {
                int hl2 = hq * 2 + hh;
                int hg = h0 + hl2;
                float rf = rs[(0 * 8 + hl2) * RSP + pb];
                float ri = rs[(1 * 8 + hl2) * RSP + pb];
                float ro = rs[(2 * 8 + hl2) * RSP + pb];
                float gf = hh ? gv[0].y : gv[0].x;
                float gi = hh ? gv[1].y : gv[1].x;
                float go = hh ? gv[2].y : gv[2].x;
                float tc = hh ? gv[3].y : gv[3].x;   // pre-tanh'd
                float cprev = hh ? creg1 : creg0;
                float f  = 1.f / (1.f + __expf(-(gf + rf)));
                float ii = 1.f / (1.f + __expf(-(gi + ri)));
                float o  = 1.f / (1.f + __expf(-(go + ro)));
                float cn = f * cprev + ii * tc;
                float hv = o * tanhf(cn);
                if (hh) creg1 = cn; else creg0 = cn;
                ctb[hl2 * CBP + pb] = cn;
                out[((size_t)pb * Tt + t) * Hh + hg] = hv;
                if (write_tail && t == Tt - 1)
                    out[(size_t)Bb * Tt * Hh + (size_t)pb * Hh + hg] = hv;
            }
        }
        __syncthreads();
        // transposed, coalesced ct store: ctT_out[h0+hl][0:64]
        if (tid < 128) {
            int hl = tid >> 4, u = tid & 15;
            float4 v = *(float4*)(ctb + hl * CBP + u * 4);
            *(float4*)(ct_out + (h0 + hl) * 64 + u * 4) = v;
        }

        // ---- grid barrier ----
        __syncthreads();
        __threadfence();
        if (tid == 0) {
            atomicAdd(&g_bar, 1u);
            unsigned target = (unsigned)(t + 1) * NB;
            while (*((volatile unsigned*)&g_bar) < target) { }
        }
        __syncthreads();
        __threadfence();
    }
}

// ---------------- launch ----------------
extern "C" void kernel_launch(void* const* d_in, const int* in_sizes, int n_in,
                              void* d_out, int out_size) {
    const float* x   = (const float*)d_in[0];
    const float* Wxf = (const float*)d_in[1];
    const float* Wcf = (const float*)d_in[2];
    const float* bcf = (const float*)d_in[3];
    const float* Wxi = (const float*)d_in[4];
    const float* Wci = (const float*)d_in[5];
    const float* bci = (const float*)d_in[6];
    const float* Wxo = (const float*)d_in[7];
    const float* Wco = (const float*)d_in[8];
    const float* bco = (const float*)d_in[9];
    const float* Wxc = (const float*)d_in[10];
    const float* bxc = (const float*)d_in[11];
    const float* c0  = (const float*)d_in[12];
    float* out = (float*)d_out;
    int write_tail = (out_size >= Bb * Tt * Hh + Bb * Hh) ? 1 : 0;

    static int smem_set = 0;
    if (!smem_set) {
        cudaFuncSetAttribute(rec_persist_kernel,
                             cudaFuncAttributeMaxDynamicSharedMemorySize,
                             SMEM_FLOATS * (int)sizeof(float));
        smem_set = 1;
    }

    init_kernel<<<256, 256>>>(c0);
    proj_kernel<<<dim3(256, 32), 256>>>(x, Wxf, Wxi, Wxo, Wxc, bcf, bci, bco, bxc);
    rec_persist_kernel<<<NB, TPB, SMEM_FLOATS * sizeof(float)>>>(
        Wcf, Wci, Wco, c0, out, write_tail);
}

// round 8
// speedup vs baseline: 1.3383x; 1.1085x over previous
#include <cuda_runtime.h>
#include <math.h>

#define Bb 64
#define Tt 512
#define INN 1024
#define Hh 1024

#define NB 128      // persistent blocks
#define TPB 384     // tid = kg + 16*m, m = bg + 8*cg (kg 0-15, bg 0-7, cg 0-2)

typedef unsigned long long ull;

// ---------------- scratch (device globals; no allocation allowed) ----------------
__device__ __align__(16) float g_pre[4ull * Tt * Bb * Hh];  // [gate][t][b][h] (512 MB)
__device__ __align__(16) float ctT_buf[2][Hh * Bb];         // cell state, TRANSPOSED [h][b]
__device__ unsigned g_bar = 0;                              // grid barrier counter

// ---------------- fp32x2 packed helpers ----------------
__device__ __forceinline__ ull pk2(float lo, float hi) {
    ull r; asm("mov.b64 %0, {%1,%2};" : "=l"(r) : "f"(lo), "f"(hi)); return r;
}
__device__ __forceinline__ void unpk2(ull v, float& lo, float& hi) {
    asm("mov.b64 {%0,%1}, %2;" : "=f"(lo), "=f"(hi) : "l"(v));
}
__device__ __forceinline__ void fma2(ull& d, ull a, ull b) {
    asm("fma.rn.f32x2 %0, %1, %2, %3;" : "=l"(d) : "l"(a), "l"(b), "l"(d));
}
__device__ __forceinline__ void add2(ull& d, ull a) {
    asm("add.rn.f32x2 %0, %1, %2;" : "=l"(d) : "l"(d), "l"(a));
}

// ---------------- cp.async helpers ----------------
__device__ __forceinline__ void cpasync16(unsigned saddr, const void* g) {
    asm volatile("cp.async.cg.shared.global [%0], [%1], 16;" :: "r"(saddr), "l"(g));
}
#define CP_COMMIT() asm volatile("cp.async.commit_group;" ::: "memory")
#define CP_WAIT0()  asm volatile("cp.async.wait_group 0;" ::: "memory")

// ---------------- init: transposed cell state from c0 + barrier reset ----------------
__global__ void init_kernel(const float* __restrict__ c0) {
    int i = blockIdx.x * 256 + threadIdx.x;  // 65536 total; h = i>>6, b = i&63
    ctT_buf[0][i] = c0[i >> 6];
    if (i == 0) g_bar = 0;
}

// ---------------- input projections: g_pre[gate][t][b][h] = x @ Wx^T + bias -----
__global__ __launch_bounds__(256) void proj_kernel(
    const float* __restrict__ x,
    const float* __restrict__ Wf, const float* __restrict__ Wi,
    const float* __restrict__ Wo, const float* __restrict__ Wc,
    const float* __restrict__ bf, const float* __restrict__ bi,
    const float* __restrict__ bo, const float* __restrict__ bc) {
    __shared__ float As[8][128];
    __shared__ float Bs[8][128];

    int gate = blockIdx.y >> 3;
    int n0 = (blockIdx.y & 7) * 128;
    int m0 = blockIdx.x * 128;
    const float* W    = (gate == 0) ? Wf : (gate == 1) ? Wi : (gate == 2) ? Wo : Wc;
    const float* bias = (gate == 0) ? bf : (gate == 1) ? bi : (gate == 2) ? bo : bc;

    int tid = threadIdx.x;
    int tx = tid & 15;
    int ty = tid >> 4;
    int lr = tid >> 1;
    int lc = (tid & 1) * 4;
    const float* Ag = x + (size_t)(m0 + lr) * INN + lc;
    const float* Bg = W + (size_t)(n0 + lr) * INN + lc;

    ull acc2[8][4];
#pragma unroll
    for (int i = 0; i < 8; i++)
#pragma unroll
        for (int j = 0; j < 4; j++) acc2[i][j] = 0ull;

    for (int k0 = 0; k0 < INN; k0 += 8) {
        float4 av = *(const float4*)(Ag + k0);
        float4 bv = *(const float4*)(Bg + k0);
        As[lc + 0][lr] = av.x; As[lc + 1][lr] = av.y;
        As[lc + 2][lr] = av.z; As[lc + 3][lr] = av.w;
        Bs[lc + 0][lr] = bv.x; Bs[lc + 1][lr] = bv.y;
        Bs[lc + 2][lr] = bv.z; Bs[lc + 3][lr] = bv.w;
        __syncthreads();
#pragma unroll
        for (int kk = 0; kk < 8; kk++) {
            float4 a0 = *(const float4*)&As[kk][ty * 8];
            float4 a1 = *(const float4*)&As[kk][ty * 8 + 4];
            float a[8] = {a0.x, a0.y, a0.z, a0.w, a1.x, a1.y, a1.z, a1.w};
            float4 b0 = *(const float4*)&Bs[kk][tx * 8];
            float4 b1 = *(const float4*)&Bs[kk][tx * 8 + 4];
            ull bp[4] = {pk2(b0.x, b0.y), pk2(b0.z, b0.w),
                         pk2(b1.x, b1.y), pk2(b1.z, b1.w)};
#pragma unroll
            for (int i = 0; i < 8; i++) {
                ull ap = pk2(a[i], a[i]);
#pragma unroll
                for (int j = 0; j < 4; j++) fma2(acc2[i][j], ap, bp[j]);
            }
        }
        __syncthreads();
    }

#pragma unroll
    for (int i = 0; i < 8; i++) {
        int r = m0 + ty * 8 + i;
        int b_ = r >> 9;
        int t_ = r & (Tt - 1);
        float* dst = g_pre + (((size_t)gate * Tt + t_) * Bb + b_) * Hh + n0 + tx * 8;
#pragma unroll
        for (int j = 0; j < 4; j++) {
            float lo, hi;
            unpk2(acc2[i][j], lo, hi);
            int hcol = n0 + tx * 8 + 2 * j;
            float v0 = lo + bias[hcol];
            float v1 = hi + bias[hcol + 1];
            if (gate == 3) { v0 = tanhf(v0); v1 = tanhf(v1); }
            *(float2*)(dst + 2 * j) = make_float2(v0, v1);
        }
    }
}

// ---------------- persistent recurrence ----------------
// Block owns h-tile [h0,h0+8) x 3 gates = 24 cols, all 64 b.
// Thread (kg,cg,bg): 8 cols x 8 b reg tile, k = kg mod 16 interleaved, depth 64.
// SMEM: Ws[1024][28] (once), cts[2][128][68] (cp.async double buffer), rs, ctb.
// LDS.128 bank check (16B-unit mod 8): ct: kl*17+bg*2 -> kg distinct per octet.
//                                      w:  kl*7 +cg*2 -> kg distinct per octet.
#define WP  28
#define CTP 68
#define RSP 68
#define CBP 68
#define CTS_FLOATS (128 * CTP)
#define SMEM_FLOATS (1024 * WP + 2 * CTS_FLOATS + 24 * RSP + 8 * CBP)

__global__ __launch_bounds__(TPB, 1) void rec_persist_kernel(
    const float* __restrict__ Wcf, const float* __restrict__ Wci,
    const float* __restrict__ Wco, const float* __restrict__ c0,
    float* __restrict__ out, int write_tail) {
    extern __shared__ float sm[];
    float* Ws  = sm;                       // [1024][28]  Ws[k*WP+col]
    float* cts = Ws + 1024 * WP;           // [2][128][68]
    float* rs  = cts + 2 * CTS_FLOATS;     // [24][68]
    float* ctb = rs + 24 * RSP;            // [8][68]

    int tid = threadIdx.x;
    int h0 = blockIdx.x * 8;

    // ---- weights into SMEM once: Ws[k][col] = W_gate[h0+col%8][k] ----
#pragma unroll 1
    for (int col = 0; col < 24; col++) {
        const float* src = ((col < 8) ? Wcf : (col < 16) ? Wci : Wco)
                           + (size_t)(h0 + (col & 7)) * Hh;
        for (int k = tid; k < Hh; k += TPB)
            Ws[k * WP + col] = src[k];
    }

    int kg = tid & 15, m = tid >> 4;
    int cg = m >> 3, bg = m & 7;

    // pointwise identity: b = tid>>2, h-quarter = tid&3 (2 h each)
    int pb = tid >> 2;
    int hq = tid & 3;
    float creg0 = 0.f, creg1 = 0.f;
    if (tid < 256) { creg0 = c0[h0 + hq * 2]; creg1 = c0[h0 + hq * 2 + 1]; }

    // cp.async smem byte addresses for this thread's staging slots
    unsigned cts_saddr = (unsigned)__cvta_generic_to_shared(cts);
    __syncthreads();

    for (int t = 0; t < Tt; t++) {
        const float* ct_in = ctT_buf[t & 1];
        float* ct_out = ctT_buf[(t & 1) ^ 1];

        // gate prefetch for pointwise (used ~12K cycles later)
        float2 gv[4];
        if (tid < 256) {
            size_t gb = (size_t)t * Bb * Hh + (size_t)pb * Hh + h0 + hq * 2;
#pragma unroll
            for (int g = 0; g < 4; g++)
                gv[g] = __ldcg((const float2*)(g_pre + (size_t)g * Tt * Bb * Hh + gb));
        }

        // issue chunk 0 stage (cp.async: no registers, L2-direct)
#pragma unroll
        for (int i = 0; i < 6; i++) {
            int idx4 = tid + i * TPB;            // 16B unit within 32KB chunk
            if (idx4 < 2048) {
                unsigned sa = cts_saddr + ((idx4 >> 4) * CTP + (idx4 & 15) * 4) * 4;
                cpasync16(sa, (const char*)ct_in + idx4 * 16);
            }
        }
        CP_COMMIT();

        ull acc[32];
#pragma unroll
        for (int q = 0; q < 32; q++) acc[q] = 0ull;

#pragma unroll 1
        for (int c = 0; c < 8; c++) {
            CP_WAIT0();
            __syncthreads();                     // chunk c visible; buf^1 free
            if (c < 7) {
                const char* src = (const char*)(ct_in + (c + 1) * 128 * 64);
                unsigned base = cts_saddr + ((c + 1) & 1) * CTS_FLOATS * 4;
#pragma unroll
                for (int i = 0; i < 6; i++) {
                    int idx4 = tid + i * TPB;
                    if (idx4 < 2048) {
                        unsigned sa = base + ((idx4 >> 4) * CTP + (idx4 & 15) * 4) * 4;
                        cpasync16(sa, src + idx4 * 16);
                    }
                }
                CP_COMMIT();
            }
            const float* cbuf = cts + (c & 1) * CTS_FLOATS;
            // compute chunk: k = c*128 + kg + 16j
#pragma unroll 2
            for (int j = 0; j < 8; j++) {
                int kl = kg + 16 * j;
                const float* wr = Ws + (c * 128 + kl) * WP + cg * 8;
                const float* cr = cbuf + kl * CTP + bg * 8;
                ulonglong2 c01 = *(const ulonglong2*)cr;        // LDS.128, conflict-free
                ulonglong2 c23 = *(const ulonglong2*)(cr + 4);
                float4 w0 = *(const float4*)wr;                 // LDS.128, conflict-free
                float4 w1 = *(const float4*)(wr + 4);
                ull ctp[4] = {c01.x, c01.y, c23.x, c23.y};
                float wv[8] = {w0.x, w0.y, w0.z, w0.w, w1.x, w1.y, w1.z, w1.w};
#pragma unroll
                for (int ci = 0; ci < 8; ci++) {
                    ull wd = pk2(wv[ci], wv[ci]);
#pragma unroll
                    for (int p = 0; p < 4; p++) fma2(acc[ci * 4 + p], ctp[p], wd);
                }
            }
        }

        // ---- butterfly reduce over kg (lanes 0-15 / 16-31 halves) ----
#pragma unroll
        for (int d = 1; d < 16; d <<= 1) {
#pragma unroll
            for (int q = 0; q < 32; q++) {
                ull o = __shfl_xor_sync(0xffffffffu, acc[q], d);
                add2(acc[q], o);
            }
        }
        // lane kg holds reduced slots {2kg, 2kg+1} -> rs[col][b]
        {
            int q0 = kg * 2;
#pragma unroll
            for (int e = 0; e < 2; e++) {
                int q = q0 + e;
                int ci = q >> 2, p = q & 3;
                float lo, hi;
                unpk2(acc[q], lo, hi);
                float* dst = rs + (cg * 8 + ci) * RSP + bg * 8 + 2 * p;
                dst[0] = lo; dst[1] = hi;
            }
        }
        __syncthreads();

        // ---- pointwise LSTM update (block-local) ----
        if (tid < 256) {
#pragma unroll
            for (int hh = 0; hh < 2; hh++) {
                int hl2 = hq * 2 + hh;
                int hg = h0 + hl2;
                float rf = rs[(0 * 8 + hl2) * RSP + pb];
                float ri = rs[(1 * 8 + hl2) * RSP + pb];
                float ro = rs[(2 * 8 + hl2) * RSP + pb];
                float gf = hh ? gv[0].y : gv[0].x;
                float gi = hh ? gv[1].y : gv[1].x;
                float go = hh ? gv[2].y : gv[2].x;
                float tc = hh ? gv[3].y : gv[3].x;   // pre-tanh'd
                float cprev = hh ? creg1 : creg0;
                float f  = 1.f / (1.f + __expf(-(gf + rf)));
                float ii = 1.f / (1.f + __expf(-(gi + ri)));
                float o  = 1.f / (1.f + __expf(-(go + ro)));
                float cn = f * cprev + ii * tc;
                float hv = o * tanhf(cn);
                if (hh) creg1 = cn; else creg0 = cn;
                ctb[hl2 * CBP + pb] = cn;
                out[((size_t)pb * Tt + t) * Hh + hg] = hv;
                if (write_tail && t == Tt - 1)
                    out[(size_t)Bb * Tt * Hh + (size_t)pb * Hh + hg] = hv;
            }
        }
        __syncthreads();
        // transposed, coalesced ct store: ctT_out[h0+hl][0:64]
        if (tid < 128) {
            int hl = tid >> 4, u = tid & 15;
            float4 v = *(float4*)(ctb + hl * CBP + u * 4);
            *(float4*)(ct_out + (h0 + hl) * 64 + u * 4) = v;
        }

        // ---- grid barrier (publish ct_out, then arrive+poll) ----
        __syncthreads();
        __threadfence();
        if (tid == 0) {
            atomicAdd(&g_bar, 1u);
            unsigned target = (unsigned)(t + 1) * NB;
            while (*((volatile unsigned*)&g_bar) < target) { }
        }
        __syncthreads();
    }
}

// ---------------- launch ----------------
extern "C" void kernel_launch(void* const* d_in, const int* in_sizes, int n_in,
                              void* d_out, int out_size) {
    const float* x   = (const float*)d_in[0];
    const float* Wxf = (const float*)d_in[1];
    const float* Wcf = (const float*)d_in[2];
    const float* bcf = (const float*)d_in[3];
    const float* Wxi = (const float*)d_in[4];
    const float* Wci = (const float*)d_in[5];
    const float* bci = (const float*)d_in[6];
    const float* Wxo = (const float*)d_in[7];
    const float* Wco = (const float*)d_in[8];
    const float* bco = (const float*)d_in[9];
    const float* Wxc = (const float*)d_in[10];
    const float* bxc = (const float*)d_in[11];
    const float* c0  = (const float*)d_in[12];
    float* out = (float*)d_out;
    int write_tail = (out_size >= Bb * Tt * Hh + Bb * Hh) ? 1 : 0;

    static int smem_set = 0;
    if (!smem_set) {
        cudaFuncSetAttribute(rec_persist_kernel,
                             cudaFuncAttributeMaxDynamicSharedMemorySize,
                             SMEM_FLOATS * (int)sizeof(float));
        smem_set = 1;
    }

    init_kernel<<<256, 256>>>(c0);
    proj_kernel<<<dim3(256, 32), 256>>>(x, Wxf, Wxi, Wxo, Wxc, bcf, bci, bco, bxc);
    rec_persist_kernel<<<NB, TPB, SMEM_FLOATS * sizeof(float)>>>(
        Wcf, Wci, Wco, c0, out, write_tail);
}

// round 14
// speedup vs baseline: 1.6195x; 1.2102x over previous
#include <cuda_runtime.h>
#include <cuda_bf16.h>
#include <math.h>

#define Bb 64
#define Tt 512
#define INN 1024
#define Hh 1024

#define NB 128      // persistent rec blocks
#define TPB 384

typedef unsigned long long ull;

// ---------------- scratch (device globals; no allocation allowed) ----------------
__device__ __align__(16) float g_pre[4ull * Tt * Bb * Hh];          // [gate][t][b][h] 512MB
__device__ __align__(16) __nv_bfloat16 xcat[32768ull * 3072];       // [b*T][hi|lo|hi] 192MB
__device__ __align__(16) __nv_bfloat16 wcat[4096ull * 3072];        // [gate*H][hi|hi|lo] 24MB
__device__ __align__(16) float ctT_buf[2][Hh * Bb];                 // transposed cell state
__device__ unsigned g_bar = 0;

// ---------------- fp32x2 packed helpers (rec kernel) ----------------
__device__ __forceinline__ ull pk2(float lo, float hi) {
    ull r; asm("mov.b64 %0, {%1,%2};" : "=l"(r) : "f"(lo), "f"(hi)); return r;
}
__device__ __forceinline__ void unpk2(ull v, float& lo, float& hi) {
    asm("mov.b64 {%0,%1}, %2;" : "=f"(lo), "=f"(hi) : "l"(v));
}
__device__ __forceinline__ void fma2(ull& d, ull a, ull b) {
    asm("fma.rn.f32x2 %0, %1, %2, %0;" : "+l"(d) : "l"(a), "l"(b));
}
__device__ __forceinline__ void add2(ull& d, ull a) {
    asm("add.rn.f32x2 %0, %0, %1;" : "+l"(d) : "l"(a));
}

// ---------------- cp.async helpers ----------------
__device__ __forceinline__ void cpasync16(unsigned saddr, const void* g) {
    asm volatile("cp.async.cg.shared.global [%0], [%1], 16;" :: "r"(saddr), "l"(g));
}
#define CP_COMMIT() asm volatile("cp.async.commit_group;" ::: "memory")
#define CP_WAIT(n)  asm volatile("cp.async.wait_group %0;" :: "n"(n) : "memory")

// ---------------- mma.sync helpers (baseline PTX, works on plain sm_103) --------
__device__ __forceinline__ void ldsm4(unsigned& r0, unsigned& r1, unsigned& r2,
                                      unsigned& r3, unsigned addr) {
    asm volatile("ldmatrix.sync.aligned.m8n8.x4.shared.b16 {%0,%1,%2,%3}, [%4];"
                 : "=r"(r0), "=r"(r1), "=r"(r2), "=r"(r3) : "r"(addr));
}
__device__ __forceinline__ void mma16816(float* d, const unsigned* a,
                                         unsigned b0, unsigned b1) {
    asm volatile(
        "mma.sync.aligned.m16n8k16.row.col.f32.bf16.bf16.f32 "
        "{%0,%1,%2,%3}, {%4,%5,%6,%7}, {%8,%9}, {%0,%1,%2,%3};"
        : "+f"(d[0]), "+f"(d[1]), "+f"(d[2]), "+f"(d[3])
        : "r"(a[0]), "r"(a[1]), "r"(a[2]), "r"(a[3]), "r"(b0), "r"(b1));
}

// ---------------- init: transposed cell state + barrier reset ----------------
__global__ void init_kernel(const float* __restrict__ c0) {
    int i = blockIdx.x * 256 + threadIdx.x;
    ctT_buf[0][i] = c0[i >> 6];
    if (i == 0) g_bar = 0;
}

// ---------------- bf16 split helpers ----------------
__device__ __forceinline__ void split_bf(float x, unsigned short& h, unsigned short& l) {
    __nv_bfloat16 hb = __float2bfloat16_rn(x);
    __nv_bfloat16 lb = __float2bfloat16_rn(x - __bfloat162float(hb));
    h = __bfloat16_as_ushort(hb);
    l = __bfloat16_as_ushort(lb);
}

// ---------------- convert x -> xcat [row][ hi(1024) | lo(1024) | hi(1024) ] ----
__global__ __launch_bounds__(256) void convx_kernel(const float* __restrict__ x) {
    for (size_t i = (size_t)blockIdx.x * 256 + threadIdx.x; i < 8388608ull;
         i += (size_t)gridDim.x * 256) {
        float4 v = ((const float4*)x)[i];
        int row = (int)(i >> 8);
        int k4 = (int)(i & 255);
        unsigned short h0, h1, h2, h3, l0, l1, l2, l3;
        split_bf(v.x, h0, l0); split_bf(v.y, h1, l1);
        split_bf(v.z, h2, l2); split_bf(v.w, h3, l3);
        uint2 hp = make_uint2((unsigned)h0 | ((unsigned)h1 << 16),
                              (unsigned)h2 | ((unsigned)h3 << 16));
        uint2 lp = make_uint2((unsigned)l0 | ((unsigned)l1 << 16),
                              (unsigned)l2 | ((unsigned)l3 << 16));
        __nv_bfloat16* dst = xcat + (size_t)row * 3072 + k4 * 4;
        *(uint2*)dst          = hp;
        *(uint2*)(dst + 1024) = lp;
        *(uint2*)(dst + 2048) = hp;
    }
}

// ---------------- convert W -> wcat [n][ hi | hi | lo ] ----------------
__global__ __launch_bounds__(256) void convw_kernel(
    const float* __restrict__ Wf, const float* __restrict__ Wi,
    const float* __restrict__ Wo, const float* __restrict__ Wc) {
    for (size_t i = (size_t)blockIdx.x * 256 + threadIdx.x; i < 1048576ull;
         i += (size_t)gridDim.x * 256) {
        int row = (int)(i >> 8);                              // n = gate*1024 + h
        int k4 = (int)(i & 255);
        int gate = row >> 10, h = row & 1023;
        const float* W = (gate == 0) ? Wf : (gate == 1) ? Wi : (gate == 2) ? Wo : Wc;
        float4 v = ((const float4*)(W + (size_t)h * 1024))[k4];
        unsigned short h0, h1, h2, h3, l0, l1, l2, l3;
        split_bf(v.x, h0, l0); split_bf(v.y, h1, l1);
        split_bf(v.z, h2, l2); split_bf(v.w, h3, l3);
        uint2 hp = make_uint2((unsigned)h0 | ((unsigned)h1 << 16),
                              (unsigned)h2 | ((unsigned)h3 << 16));
        uint2 lp = make_uint2((unsigned)l0 | ((unsigned)l1 << 16),
                              (unsigned)l2 | ((unsigned)l3 << 16));
        __nv_bfloat16* dst = wcat + (size_t)row * 3072 + k4 * 4;
        *(uint2*)dst          = hp;
        *(uint2*)(dst + 1024) = hp;
        *(uint2*)(dst + 2048) = lp;
    }
}

// ---------------- projections via mma.sync (HMMA): g_pre = Xcat@Wcat^T + bias ---
// Block 256 thr = 8 warps (4m x 2n). Tile M=128 N=128, K=3072 in 96 chunks of 32.
// SMEM pitch 40 bf16 (80B): ldmatrix row offsets 20 words -> mod-32 disjoint.
#define APITCH 40
#define TILE_BF (128 * APITCH)    // bf16 elems per tile buffer

__global__ __launch_bounds__(256) void proj_mma_kernel(
    const float* __restrict__ bfv, const float* __restrict__ biv,
    const float* __restrict__ bov, const float* __restrict__ bcv) {
    __shared__ __align__(16) __nv_bfloat16 As[2][TILE_BF];
    __shared__ __align__(16) __nv_bfloat16 Bs[2][TILE_BF];
    __shared__ float bias_s[128];

    int tid = threadIdx.x;
    int wid = tid >> 5, lane = tid & 31;
    int warp_m = wid & 3, warp_n = wid >> 2;
    int m0 = blockIdx.x * 128;
    int n0 = blockIdx.y * 128;
    int gate = n0 >> 10;
    int hbase = n0 & 1023;

    const float* bias = (gate == 0) ? bfv : (gate == 1) ? biv : (gate == 2) ? bov : bcv;
    if (tid < 128) bias_s[tid] = bias[hbase + tid];

    unsigned a_sb = (unsigned)__cvta_generic_to_shared(&As[0][0]);
    unsigned b_sb = (unsigned)__cvta_generic_to_shared(&Bs[0][0]);

    // cp.async staging: 512 16B units per tile (row r, quarter u: 8 bf16 each)
    auto stage = [&](int c) {
        int buf = c & 1;
#pragma unroll
        for (int i = 0; i < 2; i++) {
            int unit = tid + i * 256;
            int r = unit >> 2, u = unit & 3;
            const __nv_bfloat16* ga = xcat + (size_t)(m0 + r) * 3072 + c * 32 + u * 8;
            const __nv_bfloat16* gb = wcat + (size_t)(n0 + r) * 3072 + c * 32 + u * 8;
            unsigned off = buf * (TILE_BF * 2) + r * (APITCH * 2) + u * 16;
            cpasync16(a_sb + off, ga);
            cpasync16(b_sb + off, gb);
        }
        CP_COMMIT();
    };
    stage(0);

    float acc[2][8][4];
#pragma unroll
    for (int mt = 0; mt < 2; mt++)
#pragma unroll
        for (int nt = 0; nt < 8; nt++)
#pragma unroll
            for (int e = 0; e < 4; e++) acc[mt][nt][e] = 0.f;

    // ldmatrix lane addressing offsets (in bf16 elems)
    int a_row = warp_m * 32 + ((lane >> 3) & 1) * 8 + (lane & 7);
    int a_colg = (lane >> 4) * 8;
    int b_rowg = (lane >> 4) * 8 + (lane & 7);     // n within 16-group
    int b_colg = ((lane >> 3) & 1) * 8;            // k half within 16

    for (int c = 0; c < 96; c++) {
        if (c < 95) stage(c + 1);
        if (c < 95) { CP_WAIT(1); } else { CP_WAIT(0); }
        __syncthreads();
        int buf = c & 1;
        unsigned abase = a_sb + buf * (TILE_BF * 2);
        unsigned bbase = b_sb + buf * (TILE_BF * 2);
#pragma unroll
        for (int kk = 0; kk < 32; kk += 16) {
            unsigned af[2][4];
#pragma unroll
            for (int mt = 0; mt < 2; mt++) {
                unsigned addr = abase + ((a_row + mt * 16) * APITCH + kk + a_colg) * 2;
                ldsm4(af[mt][0], af[mt][1], af[mt][2], af[mt][3], addr);
            }
            unsigned bf[4][4];
#pragma unroll
            for (int j = 0; j < 4; j++) {  // 16-n groups within warp's 64 n
                unsigned addr = bbase +
                    ((warp_n * 64 + j * 16 + b_rowg) * APITCH + kk + b_colg) * 2;
                ldsm4(bf[j][0], bf[j][1], bf[j][2], bf[j][3], addr);
            }
#pragma unroll
            for (int mt = 0; mt < 2; mt++)
#pragma unroll
                for (int nt = 0; nt < 8; nt++) {
                    int j = nt >> 1, hi = (nt & 1) * 2;
                    mma16816(acc[mt][nt], af[mt], bf[j][hi], bf[j][hi + 1]);
                }
        }
        __syncthreads();
    }

    // epilogue: c0,c1 -> row r, cols 2q; c2,c3 -> row r+8
#pragma unroll
    for (int mt = 0; mt < 2; mt++) {
#pragma unroll
        for (int half = 0; half < 2; half++) {
            int row = m0 + warp_m * 32 + mt * 16 + (lane >> 2) + half * 8;
            int b_ = row >> 9, t_ = row & 511;
            float* orow = g_pre + (((size_t)gate * 512 + t_) * 64 + b_) * 1024 + hbase;
#pragma unroll
            for (int nt = 0; nt < 8; nt++) {
                int col = warp_n * 64 + nt * 8 + (lane & 3) * 2;
                float v0 = acc[mt][nt][half * 2]     + bias_s[col];
                float v1 = acc[mt][nt][half * 2 + 1] + bias_s[col + 1];
                if (gate == 3) { v0 = tanhf(v0); v1 = tanhf(v1); }
                *(float2*)(orow + col) = make_float2(v0, v1);
            }
        }
    }
}

// ---------------- persistent recurrence (identical to R8 passing version) ----------
#define WP  28
#define CTP 68
#define RSP 68
#define CBP 68
#define CTS_FLOATS (128 * CTP)
#define SMEM_FLOATS (1024 * WP + 2 * CTS_FLOATS + 24 * RSP + 8 * CBP)

__global__ __launch_bounds__(TPB, 1) void rec_persist_kernel(
    const float* __restrict__ Wcf, const float* __restrict__ Wci,
    const float* __restrict__ Wco, const float* __restrict__ c0,
    float* __restrict__ out, int write_tail) {
    extern __shared__ float sm[];
    float* Ws  = sm;
    float* cts = Ws + 1024 * WP;
    float* rs  = cts + 2 * CTS_FLOATS;
    float* ctb = rs + 24 * RSP;

    int tid = threadIdx.x;
    int h0 = blockIdx.x * 8;

#pragma unroll 1
    for (int col = 0; col < 24; col++) {
        const float* src = ((col < 8) ? Wcf : (col < 16) ? Wci : Wco)
                           + (size_t)(h0 + (col & 7)) * Hh;
        for (int k = tid; k < Hh; k += TPB)
            Ws[k * WP + col] = src[k];
    }

    int kg = tid & 15, m = tid >> 4;
    int cg = m >> 3, bg = m & 7;
    int pb = tid >> 2;
    int hq = tid & 3;
    float creg0 = 0.f, creg1 = 0.f;
    if (tid < 256) { creg0 = c0[h0 + hq * 2]; creg1 = c0[h0 + hq * 2 + 1]; }

    unsigned cts_saddr = (unsigned)__cvta_generic_to_shared(cts);
    __syncthreads();

    for (int t = 0; t < Tt; t++) {
        const float* ct_in = ctT_buf[t & 1];
        float* ct_out = ctT_buf[(t & 1) ^ 1];

        float2 gv[4];
        if (tid < 256) {
            size_t gb = (size_t)t * Bb * Hh + (size_t)pb * Hh + h0 + hq * 2;
#pragma unroll
            for (int g = 0; g < 4; g++)
                gv[g] = __ldcg((const float2*)(g_pre + (size_t)g * Tt * Bb * Hh + gb));
        }

#pragma unroll
        for (int i = 0; i < 6; i++) {
            int idx4 = tid + i * TPB;
            if (idx4 < 2048) {
                unsigned sa = cts_saddr + ((idx4 >> 4) * CTP + (idx4 & 15) * 4) * 4;
                cpasync16(sa, (const char*)ct_in + idx4 * 16);
            }
        }
        CP_COMMIT();

        ull acc[32];
#pragma unroll
        for (int q = 0; q < 32; q++) acc[q] = 0ull;

#pragma unroll 1
        for (int c = 0; c < 8; c++) {
            CP_WAIT(0);
            __syncthreads();
            if (c < 7) {
                const char* src = (const char*)(ct_in + (c + 1) * 128 * 64);
                unsigned base = cts_saddr + ((c + 1) & 1) * CTS_FLOATS * 4;
#pragma unroll
                for (int i = 0; i < 6; i++) {
                    int idx4 = tid + i * TPB;
                    if (idx4 < 2048) {
                        unsigned sa = base + ((idx4 >> 4) * CTP + (idx4 & 15) * 4) * 4;
                        cpasync16(sa, src + idx4 * 16);
                    }
                }
                CP_COMMIT();
            }
            const float* cbuf = cts + (c & 1) * CTS_FLOATS;
#pragma unroll 2
            for (int j = 0; j < 8; j++) {
                int kl = kg + 16 * j;
                const float* wr = Ws + (c * 128 + kl) * WP + cg * 8;
                const float* cr = cbuf + kl * CTP + bg * 8;
                ulonglong2 c01 = *(const ulonglong2*)cr;
                ulonglong2 c23 = *(const ulonglong2*)(cr + 4);
                float4 w0 = *(const float4*)wr;
                float4 w1 = *(const float4*)(wr + 4);
                ull ctp[4] = {c01.x, c01.y, c23.x, c23.y};
                float wv[8] = {w0.x, w0.y, w0.z, w0.w, w1.x, w1.y, w1.z, w1.w};
#pragma unroll
                for (int ci = 0; ci < 8; ci++) {
                    ull wd = pk2(wv[ci], wv[ci]);
#pragma unroll
                    for (int p = 0; p < 4; p++) fma2(acc[ci * 4 + p], ctp[p], wd);
                }
            }
        }

#pragma unroll
        for (int d = 1; d < 16; d <<= 1) {
#pragma unroll
            for (int q = 0; q < 32; q++) {
                ull o = __shfl_xor_sync(0xffffffffu, acc[q], d);
                add2(acc[q], o);
            }
        }
        {
            int q0 = kg * 2;
#pragma unroll
            for (int e = 0; e < 2; e++) {
                int q = q0 + e;
                int ci = q >> 2, p = q & 3;
                float lo, hi;
                unpk2(acc[q], lo, hi);
                float* dst = rs + (cg * 8 + ci) * RSP + bg * 8 + 2 * p;
                dst[0] = lo; dst[1] = hi;
            }
        }
        __syncthreads();

        if (tid < 256) {
#pragma unroll
            for (int hh = 0; hh < 2; hh++) {
                int hl2 = hq * 2 + hh;
                int hg = h0 + hl2;
                float rf = rs[(0 * 8 + hl2) * RSP + pb];
                float ri = rs[(1 * 8 + hl2) * RSP + pb];
                float ro = rs[(2 * 8 + hl2) * RSP + pb];
                float gf = hh ? gv[0].y : gv[0].x;
                float gi = hh ? gv[1].y : gv[1].x;
                float go = hh ? gv[2].y : gv[2].x;
                float tc = hh ? gv[3].y : gv[3].x;
                float cprev = hh ? creg1 : creg0;
                float f  = 1.f / (1.f + __expf(-(gf + rf)));
                float ii = 1.f / (1.f + __expf(-(gi + ri)));
                float o  = 1.f / (1.f + __expf(-(go + ro)));
                float cn = f * cprev + ii * tc;
                float hv = o * tanhf(cn);
                if (hh) creg1 = cn; else creg0 = cn;
                ctb[hl2 * CBP + pb] = cn;
                out[((size_t)pb * Tt + t) * Hh + hg] = hv;
                if (write_tail && t == Tt - 1)
                    out[(size_t)Bb * Tt * Hh + (size_t)pb * Hh + hg] = hv;
            }
        }
        __syncthreads();
        if (tid < 128) {
            int hl = tid >> 4, u = tid & 15;
            float4 v = *(float4*)(ctb + hl * CBP + u * 4);
            *(float4*)(ct_out + (h0 + hl) * 64 + u * 4) = v;
        }

        __syncthreads();
        __threadfence();
        if (tid == 0) {
            atomicAdd(&g_bar, 1u);
            unsigned target = (unsigned)(t + 1) * NB;
            while (*((volatile unsigned*)&g_bar) < target) { }
        }
        __syncthreads();
    }
}

// ---------------- launch ----------------
extern "C" void kernel_launch(void* const* d_in, const int* in_sizes, int n_in,
                              void* d_out, int out_size) {
    const float* x   = (const float*)d_in[0];
    const float* Wxf = (const float*)d_in[1];
    const float* Wcf = (const float*)d_in[2];
    const float* bcf = (const float*)d_in[3];
    const float* Wxi = (const float*)d_in[4];
    const float* Wci = (const float*)d_in[5];
    const float* bci = (const float*)d_in[6];
    const float* Wxo = (const float*)d_in[7];
    const float* Wco = (const float*)d_in[8];
    const float* bco = (const float*)d_in[9];
    const float* Wxc = (const float*)d_in[10];
    const float* bxc = (const float*)d_in[11];
    const float* c0  = (const float*)d_in[12];
    float* out = (float*)d_out;
    int write_tail = (out_size >= Bb * Tt * Hh + Bb * Hh) ? 1 : 0;

    static int attr_set = 0;
    if (!attr_set) {
        cudaFuncSetAttribute(rec_persist_kernel,
                             cudaFuncAttributeMaxDynamicSharedMemorySize,
                             SMEM_FLOATS * (int)sizeof(float));
        attr_set = 1;
    }

    init_kernel<<<256, 256>>>(c0);
    convx_kernel<<<2048, 256>>>(x);
    convw_kernel<<<1024, 256>>>(Wxf, Wxi, Wxo, Wxc);
    proj_mma_kernel<<<dim3(256, 32), 256>>>(bcf, bci, bco, bxc);
    rec_persist_kernel<<<NB, TPB, SMEM_FLOATS * sizeof(float)>>>(
        Wcf, Wci, Wco, c0, out, write_tail);
}

// round 17
// speedup vs baseline: 2.5684x; 1.5859x over previous
#include <cuda_runtime.h>
#include <cuda_bf16.h>
#include <math.h>

#define Bb 64
#define Tt 512
#define INN 1024
#define Hh 1024

#define NB 128      // persistent rec blocks
#define TPB 384

typedef unsigned long long ull;

// ---------------- scratch (device globals; no allocation allowed) ----------------
__device__ __align__(16) float g_pre[4ull * Tt * Bb * Hh];          // [gate][t][b][h] 512MB
__device__ __align__(16) __nv_bfloat16 xcat[32768ull * 3072];       // proj A [b*T][hi|lo|hi]
__device__ __align__(16) __nv_bfloat16 wcat[4096ull * 3072];        // proj B [gate*H][hi|hi|lo]
__device__ __align__(16) __nv_bfloat16 wrcat[3072ull * 2048];       // rec W [g*H+h][Whi|Wlo]
__device__ __align__(16) __nv_bfloat16 ctcat_buf[2][Bb * 2048];     // cell state [b][hi|lo] bf16
__device__ unsigned g_bar = 0;

// ---------------- cp.async helpers ----------------
__device__ __forceinline__ void cpasync16(unsigned saddr, const void* g) {
    asm volatile("cp.async.cg.shared.global [%0], [%1], 16;" :: "r"(saddr), "l"(g));
}
#define CP_COMMIT() asm volatile("cp.async.commit_group;" ::: "memory")
#define CP_WAIT(n)  asm volatile("cp.async.wait_group %0;" :: "n"(n) : "memory")

// ---------------- mma.sync helpers (baseline PTX, plain sm_103 OK) --------------
__device__ __forceinline__ void ldsm4(unsigned& r0, unsigned& r1, unsigned& r2,
                                      unsigned& r3, unsigned addr) {
    asm volatile("ldmatrix.sync.aligned.m8n8.x4.shared.b16 {%0,%1,%2,%3}, [%4];"
                 : "=r"(r0), "=r"(r1), "=r"(r2), "=r"(r3) : "r"(addr));
}
__device__ __forceinline__ void mma16816(float* d, const unsigned* a,
                                         unsigned b0, unsigned b1) {
    asm volatile(
        "mma.sync.aligned.m16n8k16.row.col.f32.bf16.bf16.f32 "
        "{%0,%1,%2,%3}, {%4,%5,%6,%7}, {%8,%9}, {%0,%1,%2,%3};"
        : "+f"(d[0]), "+f"(d[1]), "+f"(d[2]), "+f"(d[3])
        : "r"(a[0]), "r"(a[1]), "r"(a[2]), "r"(a[3]), "r"(b0), "r"(b1));
}

// ---------------- bf16 split helpers ----------------
__device__ __forceinline__ void split_bf(float x, unsigned short& h, unsigned short& l) {
    __nv_bfloat16 hb = __float2bfloat16_rn(x);
    __nv_bfloat16 lb = __float2bfloat16_rn(x - __bfloat162float(hb));
    h = __bfloat16_as_ushort(hb);
    l = __bfloat16_as_ushort(lb);
}

// ---------------- init: ctcat from c0 + barrier reset ----------------
__global__ void init_kernel(const float* __restrict__ c0) {
    int i = blockIdx.x * 256 + threadIdx.x;   // 65536: b = i>>10, h = i&1023
    int b = i >> 10, h = i & 1023;
    unsigned short hi, lo;
    split_bf(c0[h], hi, lo);
    ctcat_buf[0][b * 2048 + h]        = __ushort_as_bfloat16(hi);
    ctcat_buf[0][b * 2048 + 1024 + h] = __ushort_as_bfloat16(lo);
    if (i == 0) g_bar = 0;
}

// ---------------- convert x -> xcat [row][ hi(1024) | lo(1024) | hi(1024) ] ----
__global__ __launch_bounds__(256) void convx_kernel(const float* __restrict__ x) {
    for (size_t i = (size_t)blockIdx.x * 256 + threadIdx.x; i < 8388608ull;
         i += (size_t)gridDim.x * 256) {
        float4 v = ((const float4*)x)[i];
        int row = (int)(i >> 8);
        int k4 = (int)(i & 255);
        unsigned short h0, h1, h2, h3, l0, l1, l2, l3;
        split_bf(v.x, h0, l0); split_bf(v.y, h1, l1);
        split_bf(v.z, h2, l2); split_bf(v.w, h3, l3);
        uint2 hp = make_uint2((unsigned)h0 | ((unsigned)h1 << 16),
                              (unsigned)h2 | ((unsigned)h3 << 16));
        uint2 lp = make_uint2((unsigned)l0 | ((unsigned)l1 << 16),
                              (unsigned)l2 | ((unsigned)l3 << 16));
        __nv_bfloat16* dst = xcat + (size_t)row * 3072 + k4 * 4;
        *(uint2*)dst          = hp;
        *(uint2*)(dst + 1024) = lp;
        *(uint2*)(dst + 2048) = hp;
    }
}

// ---------------- convert W -> wcat [n][ hi | hi | lo ] (proj B) ----------------
__global__ __launch_bounds__(256) void convw_kernel(
    const float* __restrict__ Wf, const float* __restrict__ Wi,
    const float* __restrict__ Wo, const float* __restrict__ Wc) {
    for (size_t i = (size_t)blockIdx.x * 256 + threadIdx.x; i < 1048576ull;
         i += (size_t)gridDim.x * 256) {
        int row = (int)(i >> 8);
        int k4 = (int)(i & 255);
        int gate = row >> 10, h = row & 1023;
        const float* W = (gate == 0) ? Wf : (gate == 1) ? Wi : (gate == 2) ? Wo : Wc;
        float4 v = ((const float4*)(W + (size_t)h * 1024))[k4];
        unsigned short h0, h1, h2, h3, l0, l1, l2, l3;
        split_bf(v.x, h0, l0); split_bf(v.y, h1, l1);
        split_bf(v.z, h2, l2); split_bf(v.w, h3, l3);
        uint2 hp = make_uint2((unsigned)h0 | ((unsigned)h1 << 16),
                              (unsigned)h2 | ((unsigned)h3 << 16));
        uint2 lp = make_uint2((unsigned)l0 | ((unsigned)l1 << 16),
                              (unsigned)l2 | ((unsigned)l3 << 16));
        __nv_bfloat16* dst = wcat + (size_t)row * 3072 + k4 * 4;
        *(uint2*)dst          = hp;
        *(uint2*)(dst + 1024) = hp;
        *(uint2*)(dst + 2048) = lp;
    }
}

// ---------------- convert rec W -> wrcat [g*1024+h][ Whi(1024) | Wlo(1024) ] ----
__global__ __launch_bounds__(256) void convwrec_kernel(
    const float* __restrict__ Wf, const float* __restrict__ Wi,
    const float* __restrict__ Wo) {
    for (size_t i = (size_t)blockIdx.x * 256 + threadIdx.x; i < 786432ull;
         i += (size_t)gridDim.x * 256) {
        int row = (int)(i >> 8);
        int k4 = (int)(i & 255);
        int gate = row >> 10, h = row & 1023;
        const float* W = (gate == 0) ? Wf : (gate == 1) ? Wi : Wo;
        float4 v = ((const float4*)(W + (size_t)h * 1024))[k4];
        unsigned short h0, h1, h2, h3, l0, l1, l2, l3;
        split_bf(v.x, h0, l0); split_bf(v.y, h1, l1);
        split_bf(v.z, h2, l2); split_bf(v.w, h3, l3);
        uint2 hp = make_uint2((unsigned)h0 | ((unsigned)h1 << 16),
                              (unsigned)h2 | ((unsigned)h3 << 16));
        uint2 lp = make_uint2((unsigned)l0 | ((unsigned)l1 << 16),
                              (unsigned)l2 | ((unsigned)l3 << 16));
        __nv_bfloat16* dst = wrcat + (size_t)row * 2048 + k4 * 4;
        *(uint2*)dst          = hp;
        *(uint2*)(dst + 1024) = lp;
    }
}

// ---------------- projections via mma.sync (unchanged, passing) ----------------
#define APITCH 40
#define TILE_BF (128 * APITCH)

__global__ __launch_bounds__(256) void proj_mma_kernel(
    const float* __restrict__ bfv, const float* __restrict__ biv,
    const float* __restrict__ bov, const float* __restrict__ bcv) {
    __shared__ __align__(16) __nv_bfloat16 As[2][TILE_BF];
    __shared__ __align__(16) __nv_bfloat16 Bs[2][TILE_BF];
    __shared__ float bias_s[128];

    int tid = threadIdx.x;
    int wid = tid >> 5, lane = tid & 31;
    int warp_m = wid & 3, warp_n = wid >> 2;
    int m0 = blockIdx.x * 128;
    int n0 = blockIdx.y * 128;
    int gate = n0 >> 10;
    int hbase = n0 & 1023;

    const float* bias = (gate == 0) ? bfv : (gate == 1) ? biv : (gate == 2) ? bov : bcv;
    if (tid < 128) bias_s[tid] = bias[hbase + tid];

    unsigned a_sb = (unsigned)__cvta_generic_to_shared(&As[0][0]);
    unsigned b_sb = (unsigned)__cvta_generic_to_shared(&Bs[0][0]);

    auto stage = [&](int c) {
        int buf = c & 1;
#pragma unroll
        for (int i = 0; i < 2; i++) {
            int unit = tid + i * 256;
            int r = unit >> 2, u = unit & 3;
            const __nv_bfloat16* ga = xcat + (size_t)(m0 + r) * 3072 + c * 32 + u * 8;
            const __nv_bfloat16* gb = wcat + (size_t)(n0 + r) * 3072 + c * 32 + u * 8;
            unsigned off = buf * (TILE_BF * 2) + r * (APITCH * 2) + u * 16;
            cpasync16(a_sb + off, ga);
            cpasync16(b_sb + off, gb);
        }
        CP_COMMIT();
    };
    stage(0);

    float acc[2][8][4];
#pragma unroll
    for (int mt = 0; mt < 2; mt++)
#pragma unroll
        for (int nt = 0; nt < 8; nt++)
#pragma unroll
            for (int e = 0; e < 4; e++) acc[mt][nt][e] = 0.f;

    int a_row = warp_m * 32 + ((lane >> 3) & 1) * 8 + (lane & 7);
    int a_colg = (lane >> 4) * 8;
    int b_rowg = (lane >> 4) * 8 + (lane & 7);
    int b_colg = ((lane >> 3) & 1) * 8;

    for (int c = 0; c < 96; c++) {
        if (c < 95) stage(c + 1);
        if (c < 95) { CP_WAIT(1); } else { CP_WAIT(0); }
        __syncthreads();
        int buf = c & 1;
        unsigned abase = a_sb + buf * (TILE_BF * 2);
        unsigned bbase = b_sb + buf * (TILE_BF * 2);
#pragma unroll
        for (int kk = 0; kk < 32; kk += 16) {
            unsigned af[2][4];
#pragma unroll
            for (int mt = 0; mt < 2; mt++) {
                unsigned addr = abase + ((a_row + mt * 16) * APITCH + kk + a_colg) * 2;
                ldsm4(af[mt][0], af[mt][1], af[mt][2], af[mt][3], addr);
            }
            unsigned bfr[4][4];
#pragma unroll
            for (int j = 0; j < 4; j++) {
                unsigned addr = bbase +
                    ((warp_n * 64 + j * 16 + b_rowg) * APITCH + kk + b_colg) * 2;
                ldsm4(bfr[j][0], bfr[j][1], bfr[j][2], bfr[j][3], addr);
            }
#pragma unroll
            for (int mt = 0; mt < 2; mt++)
#pragma unroll
                for (int nt = 0; nt < 8; nt++) {
                    int j = nt >> 1, hi = (nt & 1) * 2;
                    mma16816(acc[mt][nt], af[mt], bfr[j][hi], bfr[j][hi + 1]);
                }
        }
        __syncthreads();
    }

#pragma unroll
    for (int mt = 0; mt < 2; mt++) {
#pragma unroll
        for (int half = 0; half < 2; half++) {
            int row = m0 + warp_m * 32 + mt * 16 + (lane >> 2) + half * 8;
            int b_ = row >> 9, t_ = row & 511;
            float* orow = g_pre + (((size_t)gate * 512 + t_) * 64 + b_) * 1024 + hbase;
#pragma unroll
            for (int nt = 0; nt < 8; nt++) {
                int col = warp_n * 64 + nt * 8 + (lane & 3) * 2;
                float v0 = acc[mt][nt][half * 2]     + bias_s[col];
                float v1 = acc[mt][nt][half * 2 + 1] + bias_s[col + 1];
                if (gate == 3) { v0 = tanhf(v0); v1 = tanhf(v1); }
                *(float2*)(orow + col) = make_float2(v0, v1);
            }
        }
    }
}

// ---------------- persistent recurrence on tensor cores ----------------
// Block: h-tile [h0,h0+8) x 3 gates. Warps 0-3 = m16 b-tiles (mma); ALL threads
// stage. B (split weights, 24 x [Whi(1024)|Wlo(1024)]) SMEM-resident all steps.
// A = ctcat chunk [64 b][hi64|lo64], double buffered, CP_WAIT(0) full drain.
// B fragments via plain LDS.32 (conflict-free: word = 4*bn + (lane&3)).
#define BWP 2056                         // B pitch bf16 (4112B)
#define AP  136                          // A pitch bf16 (272B)
#define ABUF (64 * AP)
#define RSP 68
#define REC_SMEM_BF (24 * BWP + 2 * ABUF)
#define REC_SMEM_BYTES (REC_SMEM_BF * 2 + 24 * RSP * 4)

__global__ __launch_bounds__(TPB, 1) void rec_tc_kernel(
    const float* __restrict__ c0, float* __restrict__ out, int write_tail) {
    extern __shared__ __nv_bfloat16 smb[];
    __nv_bfloat16* Bw = smb;                       // [24][2056]
    __nv_bfloat16* Aw = smb + 24 * BWP;            // [2][64][136]
    float* rs = (float*)(smb + REC_SMEM_BF);       // [24][68]

    int tid = threadIdx.x;
    int wid = tid >> 5, lane = tid & 31;
    int h0 = blockIdx.x * 8;

    unsigned aw_sb = (unsigned)__cvta_generic_to_shared(Aw);
    unsigned bw_sb = (unsigned)__cvta_generic_to_shared(Bw);

    // ---- load split weights into SMEM once: 24 rows x 2048 bf16 = 6144 16B units
#pragma unroll 1
    for (int i = 0; i < 16; i++) {
        int idx = tid + i * TPB;                   // 0..6143
        int row = idx >> 8, u = idx & 255;         // 256 units per row
        const __nv_bfloat16* src =
            wrcat + (size_t)((row >> 3) * 1024 + h0 + (row & 7)) * 2048 + u * 8;
        cpasync16(bw_sb + (row * BWP + u * 8) * 2, src);
    }
    CP_COMMIT();
    CP_WAIT(0);

    // pointwise identity: b = tid>>2, h-quarter = tid&3 (2 h each)
    int pb = tid >> 2;
    int hq = tid & 3;
    float creg0 = 0.f, creg1 = 0.f;
    if (tid < 256) { creg0 = c0[h0 + hq * 2]; creg1 = c0[h0 + hq * 2 + 1]; }
    __syncthreads();

    // mma lane addressing (warps 0-3)
    int a_row = wid * 16 + ((lane >> 3) & 1) * 8 + (lane & 7);
    int a_colg = (lane >> 4) * 8;
    int bn = lane >> 2;            // n within 8 (B fragment row group)
    int bk = (lane & 3) * 2;       // k pair base within k8

    for (int t = 0; t < Tt; t++) {
        const __nv_bfloat16* ct_in = ctcat_buf[t & 1];
        __nv_bfloat16* ct_out = ctcat_buf[(t & 1) ^ 1];

        // gate prefetch for pointwise (used much later)
        float2 gv[4];
        if (tid < 256) {
            size_t gb = (size_t)t * Bb * Hh + (size_t)pb * Hh + h0 + hq * 2;
#pragma unroll
            for (int g = 0; g < 4; g++)
                gv[g] = __ldcg((const float2*)(g_pre + (size_t)g * Tt * Bb * Hh + gb));
        }

        // all-thread staging: chunk c = [64 b][hi 64 | lo 64] (1024 16B units)
        auto stage = [&](int c) {
#pragma unroll
            for (int i = 0; i < 3; i++) {
                int idx = tid + i * TPB;
                if (idx < 1024) {
                    int r = idx >> 4, u = idx & 15;
                    int gcol = (u < 8) ? (c * 64 + u * 8)
                                       : (1024 + c * 64 + (u - 8) * 8);
                    cpasync16(aw_sb + ((c & 1) * ABUF + r * AP + u * 8) * 2,
                              ct_in + (size_t)r * 2048 + gcol);
                }
            }
            CP_COMMIT();
        };
        stage(0);

        float acc[3][4];
#pragma unroll
        for (int g = 0; g < 3; g++)
#pragma unroll
            for (int e = 0; e < 4; e++) acc[g][e] = 0.f;

#pragma unroll 1
        for (int c = 0; c < 16; c++) {
            CP_WAIT(0);
            __syncthreads();                 // chunk c visible to all
            if (c < 15) stage(c + 1);        // streams into buffer (c+1)&1
            if (wid < 4) {
                unsigned abase = aw_sb + (c & 1) * ABUF * 2;
#pragma unroll
                for (int kk = 0; kk < 64; kk += 16) {
                    unsigned ah[4], al[4];
                    ldsm4(ah[0], ah[1], ah[2], ah[3],
                          abase + (a_row * AP + kk + a_colg) * 2);
                    ldsm4(al[0], al[1], al[2], al[3],
                          abase + (a_row * AP + 64 + kk + a_colg) * 2);
#pragma unroll
                    for (int g = 0; g < 3; g++) {
                        int base = (g * 8 + bn) * BWP + c * 64 + kk + bk;
                        unsigned wh0 = *(const unsigned*)(Bw + base);
                        unsigned wh1 = *(const unsigned*)(Bw + base + 8);
                        unsigned wl0 = *(const unsigned*)(Bw + base + 1024);
                        unsigned wl1 = *(const unsigned*)(Bw + base + 1032);
                        mma16816(acc[g], ah, wh0, wh1);   // hi * Whi
                        mma16816(acc[g], al, wh0, wh1);   // lo * Whi
                        mma16816(acc[g], ah, wl0, wl1);   // hi * Wlo
                    }
                }
            }
        }

        // epilogue: warps 0-3 write acc -> rs[col = g*8+n][b]
        if (wid < 4) {
#pragma unroll
            for (int g = 0; g < 3; g++)
#pragma unroll
                for (int e = 0; e < 4; e++) {
                    int col = g * 8 + (lane & 3) * 2 + (e & 1);
                    int bb = wid * 16 + (lane >> 2) + (e >> 1) * 8;
                    rs[col * RSP + bb] = acc[g][e];
                }
        }
        __syncthreads();

        // ---- pointwise LSTM update (block-local) ----
        if (tid < 256) {
            unsigned short chh[2], cll[2];
#pragma unroll
            for (int hh = 0; hh < 2; hh++) {
                int hl2 = hq * 2 + hh;
                int hg = h0 + hl2;
                float rf = rs[(0 * 8 + hl2) * RSP + pb];
                float ri = rs[(1 * 8 + hl2) * RSP + pb];
                float ro = rs[(2 * 8 + hl2) * RSP + pb];
                float gf = hh ? gv[0].y : gv[0].x;
                float gi = hh ? gv[1].y : gv[1].x;
                float go = hh ? gv[2].y : gv[2].x;
                float tc = hh ? gv[3].y : gv[3].x;   // pre-tanh'd
                float cprev = hh ? creg1 : creg0;
                float f  = 1.f / (1.f + __expf(-(gf + rf)));
                float ii = 1.f / (1.f + __expf(-(gi + ri)));
                float o  = 1.f / (1.f + __expf(-(go + ro)));
                float cn = f * cprev + ii * tc;
                float hv = o * tanhf(cn);
                if (hh) creg1 = cn; else creg0 = cn;
                split_bf(cn, chh[hh], cll[hh]);
                out[((size_t)pb * Tt + t) * Hh + hg] = hv;
                if (write_tail && t == Tt - 1)
                    out[(size_t)Bb * Tt * Hh + (size_t)pb * Hh + hg] = hv;
            }
            int hg0 = h0 + hq * 2;
            *(unsigned*)(ct_out + (size_t)pb * 2048 + hg0) =
                (unsigned)chh[0] | ((unsigned)chh[1] << 16);
            *(unsigned*)(ct_out + (size_t)pb * 2048 + 1024 + hg0) =
                (unsigned)cll[0] | ((unsigned)cll[1] << 16);
        }

        // ---- grid barrier ----
        __syncthreads();
        __threadfence();
        if (tid == 0) {
            atomicAdd(&g_bar, 1u);
            unsigned target = (unsigned)(t + 1) * NB;
            while (*((volatile unsigned*)&g_bar) < target) { }
        }
        __syncthreads();
    }
}

// ---------------- launch ----------------
extern "C" void kernel_launch(void* const* d_in, const int* in_sizes, int n_in,
                              void* d_out, int out_size) {
    const float* x   = (const float*)d_in[0];
    const float* Wxf = (const float*)d_in[1];
    const float* Wcf = (const float*)d_in[2];
    const float* bcf = (const float*)d_in[3];
    const float* Wxi = (const float*)d_in[4];
    const float* Wci = (const float*)d_in[5];
    const float* bci = (const float*)d_in[6];
    const float* Wxo = (const float*)d_in[7];
    const float* Wco = (const float*)d_in[8];
    const float* bco = (const float*)d_in[9];
    const float* Wxc = (const float*)d_in[10];
    const float* bxc = (const float*)d_in[11];
    const float* c0  = (const float*)d_in[12];
    float* out = (float*)d_out;
    int write_tail = (out_size >= Bb * Tt * Hh + Bb * Hh) ? 1 : 0;

    static int attr_set = 0;
    if (!attr_set) {
        cudaFuncSetAttribute(rec_tc_kernel,
                             cudaFuncAttributeMaxDynamicSharedMemorySize,
                             REC_SMEM_BYTES);
        attr_set = 1;
    }

    init_kernel<<<256, 256>>>(c0);
    convx_kernel<<<2048, 256>>>(x);
    convw_kernel<<<1024, 256>>>(Wxf, Wxi, Wxo, Wxc);
    convwrec_kernel<<<1024, 256>>>(Wcf, Wci, Wco);
    proj_mma_kernel<<<dim3(256, 32), 256>>>(bcf, bci, bco, bxc);
    rec_tc_kernel<<<NB, TPB, REC_SMEM_BYTES>>>(c0, out, write_tail);
}